// round 7
// baseline (speedup 1.0000x reference)
#include <cuda_runtime.h>
#include <math.h>
#include <stdint.h>

#define BB 4
#define LL 2048
#define IN_DIM 64
#define DM 256
#define DI 512
#define DS 16
#define DCONV 4
#define DTR 16
#define NLAYERS 4
#define BL (BB*LL)   // 8192 rows

// ---------------- scratch (static __device__, no allocation) ----------------
__device__ float g_h[BL*DM];
__device__ float g_xz[BL*2*DI];
__device__ float g_u[BL*DI];
__device__ float g_dbc[BL*48];
__device__ float g_y[BL*DI];
__device__ float g_ln[BL*DM];

// ---------------- helpers ----------------------------------------------------
__device__ __forceinline__ uint32_t smem_u32(const void* p) {
    uint32_t a;
    asm("{ .reg .u64 t; cvta.to.shared.u64 t, %1; cvt.u32.u64 %0, t; }"
        : "=r"(a) : "l"(p));
    return a;
}
__device__ __forceinline__ uint32_t f2tf32(float x) {
    uint32_t u;
    asm("cvt.rna.tf32.f32 %0, %1;" : "=r"(u) : "f"(x));
    return u;
}
__device__ __forceinline__ void mma16n8k8(float* d, const uint32_t* a, const uint32_t* b) {
    asm volatile(
        "mma.sync.aligned.m16n8k8.row.col.f32.tf32.tf32.f32 "
        "{%0,%1,%2,%3}, {%4,%5,%6,%7}, {%8,%9}, {%0,%1,%2,%3};"
        : "+f"(d[0]), "+f"(d[1]), "+f"(d[2]), "+f"(d[3])
        : "r"(a[0]), "r"(a[1]), "r"(a[2]), "r"(a[3]), "r"(b[0]), "r"(b[1]));
}
__device__ __forceinline__ void cp16(uint32_t dst, const float* src, int srcsize) {
    asm volatile("cp.async.ca.shared.global [%0], [%1], 16, %2;"
                 :: "r"(dst), "l"(src), "r"(srcsize) : "memory");
}
#define CP_COMMIT()  asm volatile("cp.async.commit_group;" ::: "memory")
#define CP_WAIT(n)   asm volatile("cp.async.wait_group %0;" :: "n"(n) : "memory")

// ================== split-tf32 tensor-core GEMM: C = A @ W^T =================
// Block: 256 threads (8 warps, 4x2 -> 128x64 tile), BK=8.
// cp.async double-buffered; 18.4KB smem -> 2 blocks/SM for cross-block overlap.
#define TSTR 12   // smem row stride in words (conflict-free for quad pattern)

__global__ __launch_bounds__(256) void mma_gemm(
    const float* __restrict__ A, int lda,
    const float* __restrict__ W,
    const float* __restrict__ bias,
    const float* __restrict__ res,
    float* __restrict__ C,
    int N, int K, int act)
{
    __shared__ float sA[2][128*TSTR];
    __shared__ float sB[2][64*TSTR];

    int tid = threadIdx.x;
    int wid = tid >> 5, lid = tid & 31;
    int warp_m = wid >> 1;
    int warp_n = wid & 1;
    int bm = blockIdx.y * 128;
    int bn = blockIdx.x * 64;

    uint32_t aBase = smem_u32(&sA[0][0]);
    uint32_t bBase = smem_u32(&sB[0][0]);
    const uint32_t A_STAGE = 128*TSTR*4;
    const uint32_t B_STAGE = 64*TSTR*4;

    // A: 128 rows x 8 cols = 256 float4, 1/thread
    int ar = tid >> 1;
    int ac4 = (tid & 1) * 4;
    // B: 64 rows x 8 cols = 128 float4, threads 0..127
    int br = tid >> 1;
    int bc4 = (tid & 1) * 4;
    int bgn = bn + br;
    int bpred = (tid < 128 && bgn < N) ? 16 : 0;
    const float* bsrc_row = W + (size_t)((bgn < N) ? bgn : 0) * K;

    float acc[2][4][4];
    #pragma unroll
    for (int i = 0; i < 2; i++)
        #pragma unroll
        for (int j = 0; j < 4; j++)
            #pragma unroll
            for (int e = 0; e < 4; e++) acc[i][j][e] = 0.f;

    int nk = K >> 3;

    // prefetch stage 0
    cp16(aBase + (uint32_t)((ar*TSTR + ac4)*4), A + (size_t)(bm + ar)*lda + ac4, 16);
    if (tid < 128)
        cp16(bBase + (uint32_t)((br*TSTR + bc4)*4), bsrc_row + bc4, bpred);
    CP_COMMIT();

    for (int kc = 0; kc < nk; kc++) {
        int cur = kc & 1;
        if (kc + 1 < nk) {
            int k0 = (kc + 1) << 3;
            uint32_t so = (uint32_t)((kc + 1) & 1);
            cp16(aBase + so*A_STAGE + (uint32_t)((ar*TSTR + ac4)*4),
                 A + (size_t)(bm + ar)*lda + k0 + ac4, 16);
            if (tid < 128)
                cp16(bBase + so*B_STAGE + (uint32_t)((br*TSTR + bc4)*4),
                     bsrc_row + k0 + bc4, bpred);
            CP_COMMIT();
            CP_WAIT(1);
        } else {
            CP_WAIT(0);
        }
        __syncthreads();

        const float* cA = sA[cur];
        const float* cB = sB[cur];

        uint32_t ah[2][4], al[2][4];
        {
            int r0 = warp_m*32 + (lid >> 2);
            int c0 = lid & 3;
            #pragma unroll
            for (int im = 0; im < 2; im++) {
                const float* pa = cA + (r0 + im*16)*TSTR + c0;
                float f0 = pa[0], f1 = pa[8*TSTR], f2 = pa[4], f3 = pa[8*TSTR + 4];
                ah[im][0] = f2tf32(f0); al[im][0] = f2tf32(f0 - __uint_as_float(ah[im][0]));
                ah[im][1] = f2tf32(f1); al[im][1] = f2tf32(f1 - __uint_as_float(ah[im][1]));
                ah[im][2] = f2tf32(f2); al[im][2] = f2tf32(f2 - __uint_as_float(ah[im][2]));
                ah[im][3] = f2tf32(f3); al[im][3] = f2tf32(f3 - __uint_as_float(ah[im][3]));
            }
        }
        uint32_t bh[4][2], bl[4][2];
        {
            int n0 = warp_n*32 + (lid >> 2);
            int c0 = lid & 3;
            #pragma unroll
            for (int jn = 0; jn < 4; jn++) {
                const float* pb = cB + (n0 + jn*8)*TSTR + c0;
                float f0 = pb[0], f1 = pb[4];
                bh[jn][0] = f2tf32(f0); bl[jn][0] = f2tf32(f0 - __uint_as_float(bh[jn][0]));
                bh[jn][1] = f2tf32(f1); bl[jn][1] = f2tf32(f1 - __uint_as_float(bh[jn][1]));
            }
        }
        #pragma unroll
        for (int im = 0; im < 2; im++)
            #pragma unroll
            for (int jn = 0; jn < 4; jn++) {
                mma16n8k8(acc[im][jn], ah[im], bh[jn]);
                mma16n8k8(acc[im][jn], al[im], bh[jn]);
                mma16n8k8(acc[im][jn], ah[im], bl[jn]);
            }
        __syncthreads();
    }

    // ---- epilogue ----
    int gm0 = bm + warp_m*32 + (lid >> 2);
    int gnb = bn + warp_n*32 + 2*(lid & 3);
    #pragma unroll
    for (int im = 0; im < 2; im++) {
        #pragma unroll
        for (int jn = 0; jn < 4; jn++) {
            int gn = gnb + jn*8;
            if (gn < N) {
                float b0 = 0.f, b1 = 0.f;
                if (bias) { b0 = bias[gn]; b1 = bias[gn+1]; }
                #pragma unroll
                for (int half = 0; half < 2; half++) {
                    int gm = gm0 + im*16 + half*8;
                    float v0 = acc[im][jn][half*2+0] + b0;
                    float v1 = acc[im][jn][half*2+1] + b1;
                    if (act == 1) {
                        v0 = (v0 > 15.f) ? v0 : log1pf(__expf(v0));
                        v1 = (v1 > 15.f) ? v1 : log1pf(__expf(v1));
                    }
                    if (res) {
                        float2 rv = *(const float2*)(res + (size_t)gm*N + gn);
                        v0 += rv.x; v1 += rv.y;
                    }
                    *(float2*)(C + (size_t)gm*N + gn) = make_float2(v0, v1);
                }
            }
        }
    }
}

// ---------------- depthwise causal conv (width 4) + SiLU --------------------
__global__ void conv_silu_kernel(const float* __restrict__ xz,
                                 const float* __restrict__ convw,
                                 const float* __restrict__ convb,
                                 float* __restrict__ u)
{
    int idx = blockIdx.x * blockDim.x + threadIdx.x;
    if (idx >= BL*DI) return;
    int d  = idx & (DI-1);
    int bt = idx >> 9;
    int t  = bt & (LL-1);

    float acc = convb[d];
    #pragma unroll
    for (int k = 0; k < DCONV; k++) {
        int tt = t - (DCONV-1) + k;
        if (tt >= 0)
            acc = fmaf(xz[(size_t)(bt - (DCONV-1) + k)*(2*DI) + d],
                       convw[d*DCONV + k], acc);
    }
    float sig = 1.f / (1.f + __expf(-acc));
    u[idx] = acc * sig;
}

// ============ chunked selective scan (delta fused): block per (b,d) ==========
__global__ __launch_bounds__(256) void scan2_kernel(
    const float* __restrict__ xz,
    const float* __restrict__ u_arr,
    const float* __restrict__ dbc,
    const float* __restrict__ dtw,     // [DI, 16] layer slice
    const float* __restrict__ dtb,     // [DI]
    const float* __restrict__ a_log,
    const float* __restrict__ dparam,
    float* __restrict__ y_arr)
{
    __shared__ float s_delta[LL];
    __shared__ float s_u[LL];
    __shared__ float sC[16][17];
    __shared__ float sP[16][17];

    int bd = blockIdx.x;
    int d = bd & (DI-1), b = bd >> 9;
    int tid = threadIdx.x;
    int s = tid & 15, ck = tid >> 4;
    int t0 = ck * 128;
    int base = b * LL;

    // ---- stage A: delta = softplus(dt . dtw[d] + dtb[d]), u into smem ----
    float4 w0 = *(const float4*)(dtw + d*DTR + 0);
    float4 w1 = *(const float4*)(dtw + d*DTR + 4);
    float4 w2 = *(const float4*)(dtw + d*DTR + 8);
    float4 w3 = *(const float4*)(dtw + d*DTR + 12);
    float dtbd = dtb[d];

    for (int t = tid; t < LL; t += 256) {
        int row = base + t;
        const float4* p = (const float4*)(dbc + (size_t)row*48);
        float4 d0 = p[0], d1 = p[1], d2 = p[2], d3 = p[3];
        float a = d0.x*w0.x;
        a = fmaf(d0.y, w0.y, a); a = fmaf(d0.z, w0.z, a); a = fmaf(d0.w, w0.w, a);
        a = fmaf(d1.x, w1.x, a); a = fmaf(d1.y, w1.y, a); a = fmaf(d1.z, w1.z, a);
        a = fmaf(d1.w, w1.w, a);
        a = fmaf(d2.x, w2.x, a); a = fmaf(d2.y, w2.y, a); a = fmaf(d2.z, w2.z, a);
        a = fmaf(d2.w, w2.w, a);
        a = fmaf(d3.x, w3.x, a); a = fmaf(d3.y, w3.y, a); a = fmaf(d3.z, w3.z, a);
        a = fmaf(d3.w, w3.w, a);
        a += dtbd;
        s_delta[t] = (a > 15.f) ? a : log1pf(__expf(a));
        s_u[t] = u_arr[(size_t)row*DI + d];
    }
    __syncthreads();

    float A = -__expf(a_log[d*DS + s]);

    // ---- pass 1: chunk-local scan from h=0 ----
    float hloc = 0.f, sd = 0.f;
    #pragma unroll 4
    for (int i = 0; i < 128; i++) {
        int t = t0 + i;
        int row = base + t;
        float delta = s_delta[t];
        float uu    = s_u[t];
        float Bt    = dbc[(size_t)row*48 + DTR + s];
        float dA = __expf(delta * A);
        hloc = fmaf(dA, hloc, delta * uu * Bt);
        sd += delta;
    }
    sC[ck][s] = hloc;
    sP[ck][s] = __expf(sd * A);
    __syncthreads();

    // ---- prefix over chunks ----
    if (tid < 16) {
        float h = 0.f;
        #pragma unroll
        for (int c = 0; c < 16; c++) {
            float nh = fmaf(sP[c][tid], h, sC[c][tid]);
            sC[c][tid] = h;
            h = nh;
        }
    }
    __syncthreads();

    // ---- pass 2: rescan with true h_start, emit y ----
    float h = sC[ck][s];
    float Dp = dparam[d];
    #pragma unroll 4
    for (int i = 0; i < 128; i++) {
        int t = t0 + i;
        int row = base + t;
        float delta = s_delta[t];
        float uu    = s_u[t];
        float Bt    = dbc[(size_t)row*48 + DTR + s];
        float Ct    = dbc[(size_t)row*48 + DTR + DS + s];
        float dA = __expf(delta * A);
        h = fmaf(dA, h, delta * uu * Bt);

        float p = h * Ct;
        p += __shfl_xor_sync(0xffffffffu, p, 8);
        p += __shfl_xor_sync(0xffffffffu, p, 4);
        p += __shfl_xor_sync(0xffffffffu, p, 2);
        p += __shfl_xor_sync(0xffffffffu, p, 1);

        if (s == 0) {
            float z = xz[(size_t)row*(2*DI) + DI + d];
            float sig = 1.f / (1.f + __expf(-z));
            y_arr[(size_t)row*DI + d] = (p + uu * Dp) * (z * sig);
        }
    }
}

// ---------------- layernorm over 256 features (one warp per row) ------------
__global__ void ln_kernel(const float* __restrict__ x,
                          const float* __restrict__ w,
                          const float* __restrict__ b,
                          float* __restrict__ out)
{
    int warp = (blockIdx.x * blockDim.x + threadIdx.x) >> 5;
    int lane = threadIdx.x & 31;
    if (warp >= BL) return;
    const float* row = x + (size_t)warp*DM;

    float v[8];
    float sum = 0.f, sq = 0.f;
    #pragma unroll
    for (int k = 0; k < 8; k++) {
        v[k] = row[lane + k*32];
        sum += v[k];
        sq = fmaf(v[k], v[k], sq);
    }
    #pragma unroll
    for (int o = 16; o; o >>= 1) {
        sum += __shfl_xor_sync(0xffffffffu, sum, o);
        sq  += __shfl_xor_sync(0xffffffffu, sq,  o);
    }
    float mu  = sum * (1.f/DM);
    float var = sq * (1.f/DM) - mu*mu;
    float inv = rsqrtf(var + 1e-5f);
    #pragma unroll
    for (int k = 0; k < 8; k++) {
        int c = lane + k*32;
        out[(size_t)warp*DM + c] = (v[k]-mu)*inv*w[c] + b[c];
    }
}

// ---------------- host orchestration ----------------------------------------
static inline void launch_gemm(const float* A, int lda, const float* W,
                               const float* bias, const float* res,
                               float* C, int N, int K, int act)
{
    dim3 grid((N + 63) / 64, BL / 128);
    mma_gemm<<<grid, 256>>>(A, lda, W, bias, res, C, N, K, act);
}

extern "C" void kernel_launch(void* const* d_in, const int* in_sizes, int n_in,
                              void* d_out, int out_size)
{
    const float* x          = (const float*)d_in[0];
    const float* in_proj_w  = (const float*)d_in[1];
    const float* in_proj_b  = (const float*)d_in[2];
    const float* out_proj_w = (const float*)d_in[3];
    const float* out_proj_b = (const float*)d_in[4];
    const float* inw        = (const float*)d_in[5];
    const float* convw      = (const float*)d_in[6];
    const float* convb      = (const float*)d_in[7];
    const float* xpw        = (const float*)d_in[8];
    const float* dtw        = (const float*)d_in[9];
    const float* dtb        = (const float*)d_in[10];
    const float* a_log      = (const float*)d_in[11];
    const float* dparam     = (const float*)d_in[12];
    const float* outw       = (const float*)d_in[13];
    const float* lnw        = (const float*)d_in[14];
    const float* lnb        = (const float*)d_in[15];
    float* out = (float*)d_out;

    float *h, *xz, *u, *dbc, *y, *ln;
    cudaGetSymbolAddress((void**)&h,   g_h);
    cudaGetSymbolAddress((void**)&xz,  g_xz);
    cudaGetSymbolAddress((void**)&u,   g_u);
    cudaGetSymbolAddress((void**)&dbc, g_dbc);
    cudaGetSymbolAddress((void**)&y,   g_y);
    cudaGetSymbolAddress((void**)&ln,  g_ln);

    // h = x @ in_proj_w^T + in_proj_b
    launch_gemm(x, IN_DIM, in_proj_w, in_proj_b, nullptr, h, DM, IN_DIM, 0);

    for (int l = 0; l < NLAYERS; l++) {
        // xz = h @ inw[l]^T
        launch_gemm(h, DM, inw + (size_t)l*2*DI*DM, nullptr, nullptr, xz, 2*DI, DM, 0);
        // u = silu(causal_conv(xz[:, :DI]))
        conv_silu_kernel<<<(BL*DI)/256, 256>>>(xz, convw + l*DI*DCONV, convb + l*DI, u);
        // dbc = u @ xpw[l]^T   (N=48 with guards)
        launch_gemm(u, DI, xpw + (size_t)l*48*DI, nullptr, nullptr, dbc, 48, DI, 0);
        // chunked selective scan (delta fused) + gating
        scan2_kernel<<<BB*DI, 256>>>(xz, u, dbc,
                                     dtw + (size_t)l*DI*DTR, dtb + l*DI,
                                     a_log + (size_t)l*DI*DS, dparam + l*DI, y);
        // ln_in = y @ outw[l]^T + residual(h)
        launch_gemm(y, DI, outw + (size_t)l*DM*DI, nullptr, h, ln, DM, DI, 0);
        // h = layernorm(ln_in)
        ln_kernel<<<BL/8, 256>>>(ln, lnw + l*DM, lnb + l*DM, h);
    }

    // out = h @ out_proj_w^T + out_proj_b
    launch_gemm(h, DM, out_proj_w, out_proj_b, nullptr, out, DM, DM, 0);
}

// round 8
// speedup vs baseline: 1.0662x; 1.0662x over previous
#include <cuda_runtime.h>
#include <math.h>
#include <stdint.h>

#define BB 4
#define LL 2048
#define IN_DIM 64
#define DM 256
#define DI 512
#define DS 16
#define DCONV 4
#define DTR 16
#define NLAYERS 4
#define BL (BB*LL)   // 8192 rows

// ---------------- scratch (static __device__, no allocation) ----------------
__device__ float g_h[BL*DM];
__device__ float g_xz[BL*2*DI];
__device__ float g_u[BL*DI];
__device__ float g_dbc[BL*48];
__device__ float g_y[BL*DI];
__device__ float g_ln[BL*DM];

// ---------------- helpers ----------------------------------------------------
__device__ __forceinline__ uint32_t smem_u32(const void* p) {
    uint32_t a;
    asm("{ .reg .u64 t; cvta.to.shared.u64 t, %1; cvt.u32.u64 %0, t; }"
        : "=r"(a) : "l"(p));
    return a;
}
__device__ __forceinline__ uint32_t f2tf32(float x) {
    uint32_t u;
    asm("cvt.rna.tf32.f32 %0, %1;" : "=r"(u) : "f"(x));
    return u;
}
__device__ __forceinline__ void mma16n8k8(float* d, const uint32_t* a, const uint32_t* b) {
    asm volatile(
        "mma.sync.aligned.m16n8k8.row.col.f32.tf32.tf32.f32 "
        "{%0,%1,%2,%3}, {%4,%5,%6,%7}, {%8,%9}, {%0,%1,%2,%3};"
        : "+f"(d[0]), "+f"(d[1]), "+f"(d[2]), "+f"(d[3])
        : "r"(a[0]), "r"(a[1]), "r"(a[2]), "r"(a[3]), "r"(b[0]), "r"(b[1]));
}
__device__ __forceinline__ void cp16(uint32_t dst, const float* src, int srcsize) {
    asm volatile("cp.async.ca.shared.global [%0], [%1], 16, %2;"
                 :: "r"(dst), "l"(src), "r"(srcsize) : "memory");
}
#define CP_COMMIT()  asm volatile("cp.async.commit_group;" ::: "memory")
#define CP_WAIT(n)   asm volatile("cp.async.wait_group %0;" :: "n"(n) : "memory")

// ================== split-tf32 tensor-core GEMM: C = A @ W^T =================
// Template on (BMT, NT): BMT x 64 tile, NT threads, warp tile 32x32.
// BK=16, cp.async double-buffered smem (R5-proven structure).
#define TSTR 20   // smem row stride in words (conflict-free)

template<int BMT, int NT>
__global__ __launch_bounds__(NT) void mma_gemm_t(
    const float* __restrict__ A, int lda,
    const float* __restrict__ W,
    const float* __restrict__ bias,
    const float* __restrict__ res,
    float* __restrict__ C,
    int N, int K, int act)
{
    constexpr int APT = BMT * 4 / NT;   // A float4 loads / thread
    constexpr int BPT = 64 * 4 / NT;    // B float4 loads / thread

    __shared__ float sA[2][BMT*TSTR];
    __shared__ float sB[2][64*TSTR];

    int tid = threadIdx.x;
    int wid = tid >> 5, lid = tid & 31;
    int warp_m = wid >> 1;
    int warp_n = wid & 1;
    int bm = blockIdx.y * BMT;
    int bn = blockIdx.x * 64;

    uint32_t aBase = smem_u32(&sA[0][0]);
    uint32_t bBase = smem_u32(&sB[0][0]);
    const uint32_t A_STAGE = BMT*TSTR*4;
    const uint32_t B_STAGE = 64*TSTR*4;

    // per-thread load coords
    int arr[APT], ac4[APT];
    #pragma unroll
    for (int j = 0; j < APT; j++) {
        int e = tid + j*NT;
        arr[j] = e >> 2; ac4[j] = (e & 3) * 4;
    }
    int brr[BPT], bc4[BPT], bpred[BPT];
    const float* bsrc[BPT];
    #pragma unroll
    for (int j = 0; j < BPT; j++) {
        int e = tid + j*NT;
        brr[j] = e >> 2; bc4[j] = (e & 3) * 4;
        int gn = bn + brr[j];
        bpred[j] = (gn < N) ? 16 : 0;
        bsrc[j] = W + (size_t)((gn < N) ? gn : 0) * K;
    }

    float acc[2][4][4];
    #pragma unroll
    for (int i = 0; i < 2; i++)
        #pragma unroll
        for (int j = 0; j < 4; j++)
            #pragma unroll
            for (int e = 0; e < 4; e++) acc[i][j][e] = 0.f;

    int nk = K >> 4;

    // prefetch stage 0
    #pragma unroll
    for (int j = 0; j < APT; j++)
        cp16(aBase + (uint32_t)((arr[j]*TSTR + ac4[j])*4),
             A + (size_t)(bm + arr[j])*lda + ac4[j], 16);
    #pragma unroll
    for (int j = 0; j < BPT; j++)
        cp16(bBase + (uint32_t)((brr[j]*TSTR + bc4[j])*4), bsrc[j] + bc4[j], bpred[j]);
    CP_COMMIT();

    for (int kc = 0; kc < nk; kc++) {
        int cur = kc & 1;
        if (kc + 1 < nk) {
            int k0 = (kc + 1) << 4;
            uint32_t so = (uint32_t)((kc + 1) & 1);
            #pragma unroll
            for (int j = 0; j < APT; j++)
                cp16(aBase + so*A_STAGE + (uint32_t)((arr[j]*TSTR + ac4[j])*4),
                     A + (size_t)(bm + arr[j])*lda + k0 + ac4[j], 16);
            #pragma unroll
            for (int j = 0; j < BPT; j++)
                cp16(bBase + so*B_STAGE + (uint32_t)((brr[j]*TSTR + bc4[j])*4),
                     bsrc[j] + k0 + bc4[j], bpred[j]);
            CP_COMMIT();
            CP_WAIT(1);
        } else {
            CP_WAIT(0);
        }
        __syncthreads();

        const float* cA = sA[cur];
        const float* cB = sB[cur];

        #pragma unroll
        for (int ks = 0; ks < 2; ks++) {
            int kk = ks * 8;
            uint32_t ah[2][4], al[2][4];
            {
                int r0 = warp_m*32 + (lid >> 2);
                int c0 = kk + (lid & 3);
                #pragma unroll
                for (int im = 0; im < 2; im++) {
                    const float* pa = cA + (r0 + im*16)*TSTR + c0;
                    float f0 = pa[0], f1 = pa[8*TSTR], f2 = pa[4], f3 = pa[8*TSTR + 4];
                    ah[im][0] = f2tf32(f0); al[im][0] = f2tf32(f0 - __uint_as_float(ah[im][0]));
                    ah[im][1] = f2tf32(f1); al[im][1] = f2tf32(f1 - __uint_as_float(ah[im][1]));
                    ah[im][2] = f2tf32(f2); al[im][2] = f2tf32(f2 - __uint_as_float(ah[im][2]));
                    ah[im][3] = f2tf32(f3); al[im][3] = f2tf32(f3 - __uint_as_float(ah[im][3]));
                }
            }
            uint32_t bh[4][2], bl[4][2];
            {
                int n0 = warp_n*32 + (lid >> 2);
                int c0 = kk + (lid & 3);
                #pragma unroll
                for (int jn = 0; jn < 4; jn++) {
                    const float* pb = cB + (n0 + jn*8)*TSTR + c0;
                    float f0 = pb[0], f1 = pb[4];
                    bh[jn][0] = f2tf32(f0); bl[jn][0] = f2tf32(f0 - __uint_as_float(bh[jn][0]));
                    bh[jn][1] = f2tf32(f1); bl[jn][1] = f2tf32(f1 - __uint_as_float(bh[jn][1]));
                }
            }
            #pragma unroll
            for (int im = 0; im < 2; im++)
                #pragma unroll
                for (int jn = 0; jn < 4; jn++) {
                    mma16n8k8(acc[im][jn], ah[im], bh[jn]);
                    mma16n8k8(acc[im][jn], al[im], bh[jn]);
                    mma16n8k8(acc[im][jn], ah[im], bl[jn]);
                }
        }
        __syncthreads();
    }

    // ---- epilogue ----
    int gm0 = bm + warp_m*32 + (lid >> 2);
    int gnb = bn + warp_n*32 + 2*(lid & 3);
    #pragma unroll
    for (int im = 0; im < 2; im++) {
        #pragma unroll
        for (int jn = 0; jn < 4; jn++) {
            int gn = gnb + jn*8;
            if (gn < N) {
                float b0 = 0.f, b1 = 0.f;
                if (bias) { b0 = bias[gn]; b1 = bias[gn+1]; }
                #pragma unroll
                for (int half = 0; half < 2; half++) {
                    int gm = gm0 + im*16 + half*8;
                    float v0 = acc[im][jn][half*2+0] + b0;
                    float v1 = acc[im][jn][half*2+1] + b1;
                    if (act == 1) {
                        v0 = (v0 > 15.f) ? v0 : log1pf(__expf(v0));
                        v1 = (v1 > 15.f) ? v1 : log1pf(__expf(v1));
                    }
                    if (res) {
                        float2 rv = *(const float2*)(res + (size_t)gm*N + gn);
                        v0 += rv.x; v1 += rv.y;
                    }
                    *(float2*)(C + (size_t)gm*N + gn) = make_float2(v0, v1);
                }
            }
        }
    }
}

// ---------------- depthwise causal conv (width 4) + SiLU --------------------
__global__ void conv_silu_kernel(const float* __restrict__ xz,
                                 const float* __restrict__ convw,
                                 const float* __restrict__ convb,
                                 float* __restrict__ u)
{
    int idx = blockIdx.x * blockDim.x + threadIdx.x;
    if (idx >= BL*DI) return;
    int d  = idx & (DI-1);
    int bt = idx >> 9;
    int t  = bt & (LL-1);

    float acc = convb[d];
    #pragma unroll
    for (int k = 0; k < DCONV; k++) {
        int tt = t - (DCONV-1) + k;
        if (tt >= 0)
            acc = fmaf(xz[(size_t)(bt - (DCONV-1) + k)*(2*DI) + d],
                       convw[d*DCONV + k], acc);
    }
    float sig = 1.f / (1.f + __expf(-acc));
    u[idx] = acc * sig;
}

// ============ chunked selective scan (delta fused): block per (b,d) ==========
__global__ __launch_bounds__(256) void scan2_kernel(
    const float* __restrict__ xz,
    const float* __restrict__ u_arr,
    const float* __restrict__ dbc,
    const float* __restrict__ dtw,     // [DI, 16] layer slice
    const float* __restrict__ dtb,     // [DI]
    const float* __restrict__ a_log,
    const float* __restrict__ dparam,
    float* __restrict__ y_arr)
{
    __shared__ float s_delta[LL];
    __shared__ float s_u[LL];
    __shared__ float sC[16][17];
    __shared__ float sP[16][17];

    int bd = blockIdx.x;
    int d = bd & (DI-1), b = bd >> 9;
    int tid = threadIdx.x;
    int s = tid & 15, ck = tid >> 4;
    int t0 = ck * 128;
    int base = b * LL;

    // ---- stage A: delta = softplus(dt . dtw[d] + dtb[d]), u into smem ----
    float4 w0 = *(const float4*)(dtw + d*DTR + 0);
    float4 w1 = *(const float4*)(dtw + d*DTR + 4);
    float4 w2 = *(const float4*)(dtw + d*DTR + 8);
    float4 w3 = *(const float4*)(dtw + d*DTR + 12);
    float dtbd = dtb[d];

    for (int t = tid; t < LL; t += 256) {
        int row = base + t;
        const float4* p = (const float4*)(dbc + (size_t)row*48);
        float4 d0 = p[0], d1 = p[1], d2 = p[2], d3 = p[3];
        float a = d0.x*w0.x;
        a = fmaf(d0.y, w0.y, a); a = fmaf(d0.z, w0.z, a); a = fmaf(d0.w, w0.w, a);
        a = fmaf(d1.x, w1.x, a); a = fmaf(d1.y, w1.y, a); a = fmaf(d1.z, w1.z, a);
        a = fmaf(d1.w, w1.w, a);
        a = fmaf(d2.x, w2.x, a); a = fmaf(d2.y, w2.y, a); a = fmaf(d2.z, w2.z, a);
        a = fmaf(d2.w, w2.w, a);
        a = fmaf(d3.x, w3.x, a); a = fmaf(d3.y, w3.y, a); a = fmaf(d3.z, w3.z, a);
        a = fmaf(d3.w, w3.w, a);
        a += dtbd;
        s_delta[t] = (a > 15.f) ? a : log1pf(__expf(a));
        s_u[t] = u_arr[(size_t)row*DI + d];
    }
    __syncthreads();

    float A = -__expf(a_log[d*DS + s]);

    // ---- pass 1: chunk-local scan from h=0 ----
    float hloc = 0.f, sd = 0.f;
    #pragma unroll 4
    for (int i = 0; i < 128; i++) {
        int t = t0 + i;
        int row = base + t;
        float delta = s_delta[t];
        float uu    = s_u[t];
        float Bt    = dbc[(size_t)row*48 + DTR + s];
        float dA = __expf(delta * A);
        hloc = fmaf(dA, hloc, delta * uu * Bt);
        sd += delta;
    }
    sC[ck][s] = hloc;
    sP[ck][s] = __expf(sd * A);
    __syncthreads();

    // ---- prefix over chunks ----
    if (tid < 16) {
        float h = 0.f;
        #pragma unroll
        for (int c = 0; c < 16; c++) {
            float nh = fmaf(sP[c][tid], h, sC[c][tid]);
            sC[c][tid] = h;
            h = nh;
        }
    }
    __syncthreads();

    // ---- pass 2: rescan with true h_start, emit y ----
    float h = sC[ck][s];
    float Dp = dparam[d];
    #pragma unroll 4
    for (int i = 0; i < 128; i++) {
        int t = t0 + i;
        int row = base + t;
        float delta = s_delta[t];
        float uu    = s_u[t];
        float Bt    = dbc[(size_t)row*48 + DTR + s];
        float Ct    = dbc[(size_t)row*48 + DTR + DS + s];
        float dA = __expf(delta * A);
        h = fmaf(dA, h, delta * uu * Bt);

        float p = h * Ct;
        p += __shfl_xor_sync(0xffffffffu, p, 8);
        p += __shfl_xor_sync(0xffffffffu, p, 4);
        p += __shfl_xor_sync(0xffffffffu, p, 2);
        p += __shfl_xor_sync(0xffffffffu, p, 1);

        if (s == 0) {
            float z = xz[(size_t)row*(2*DI) + DI + d];
            float sig = 1.f / (1.f + __expf(-z));
            y_arr[(size_t)row*DI + d] = (p + uu * Dp) * (z * sig);
        }
    }
}

// ---------------- layernorm over 256 features (one warp per row) ------------
__global__ void ln_kernel(const float* __restrict__ x,
                          const float* __restrict__ w,
                          const float* __restrict__ b,
                          float* __restrict__ out)
{
    int warp = (blockIdx.x * blockDim.x + threadIdx.x) >> 5;
    int lane = threadIdx.x & 31;
    if (warp >= BL) return;
    const float* row = x + (size_t)warp*DM;

    float v[8];
    float sum = 0.f, sq = 0.f;
    #pragma unroll
    for (int k = 0; k < 8; k++) {
        v[k] = row[lane + k*32];
        sum += v[k];
        sq = fmaf(v[k], v[k], sq);
    }
    #pragma unroll
    for (int o = 16; o; o >>= 1) {
        sum += __shfl_xor_sync(0xffffffffu, sum, o);
        sq  += __shfl_xor_sync(0xffffffffu, sq,  o);
    }
    float mu  = sum * (1.f/DM);
    float var = sq * (1.f/DM) - mu*mu;
    float inv = rsqrtf(var + 1e-5f);
    #pragma unroll
    for (int k = 0; k < 8; k++) {
        int c = lane + k*32;
        out[(size_t)warp*DM + c] = (v[k]-mu)*inv*w[c] + b[c];
    }
}

// ---------------- host orchestration ----------------------------------------
static inline void launch_gemm_big(const float* A, int lda, const float* W,
                                   const float* bias, const float* res,
                                   float* C, int N, int K, int act)
{
    dim3 grid((N + 63) / 64, BL / 128);
    mma_gemm_t<128, 256><<<grid, 256>>>(A, lda, W, bias, res, C, N, K, act);
}
static inline void launch_gemm_small(const float* A, int lda, const float* W,
                                     const float* bias, const float* res,
                                     float* C, int N, int K, int act)
{
    dim3 grid((N + 63) / 64, BL / 64);
    mma_gemm_t<64, 128><<<grid, 128>>>(A, lda, W, bias, res, C, N, K, act);
}

extern "C" void kernel_launch(void* const* d_in, const int* in_sizes, int n_in,
                              void* d_out, int out_size)
{
    const float* x          = (const float*)d_in[0];
    const float* in_proj_w  = (const float*)d_in[1];
    const float* in_proj_b  = (const float*)d_in[2];
    const float* out_proj_w = (const float*)d_in[3];
    const float* out_proj_b = (const float*)d_in[4];
    const float* inw        = (const float*)d_in[5];
    const float* convw      = (const float*)d_in[6];
    const float* convb      = (const float*)d_in[7];
    const float* xpw        = (const float*)d_in[8];
    const float* dtw        = (const float*)d_in[9];
    const float* dtb        = (const float*)d_in[10];
    const float* a_log      = (const float*)d_in[11];
    const float* dparam     = (const float*)d_in[12];
    const float* outw       = (const float*)d_in[13];
    const float* lnw        = (const float*)d_in[14];
    const float* lnb        = (const float*)d_in[15];
    float* out = (float*)d_out;

    float *h, *xz, *u, *dbc, *y, *ln;
    cudaGetSymbolAddress((void**)&h,   g_h);
    cudaGetSymbolAddress((void**)&xz,  g_xz);
    cudaGetSymbolAddress((void**)&u,   g_u);
    cudaGetSymbolAddress((void**)&dbc, g_dbc);
    cudaGetSymbolAddress((void**)&y,   g_y);
    cudaGetSymbolAddress((void**)&ln,  g_ln);

    // h = x @ in_proj_w^T + in_proj_b
    launch_gemm_small(x, IN_DIM, in_proj_w, in_proj_b, nullptr, h, DM, IN_DIM, 0);

    for (int l = 0; l < NLAYERS; l++) {
        // xz = h @ inw[l]^T
        launch_gemm_big(h, DM, inw + (size_t)l*2*DI*DM, nullptr, nullptr, xz, 2*DI, DM, 0);
        // u = silu(causal_conv(xz[:, :DI]))
        conv_silu_kernel<<<(BL*DI)/256, 256>>>(xz, convw + l*DI*DCONV, convb + l*DI, u);
        // dbc = u @ xpw[l]^T   (N=48 with guards)
        launch_gemm_small(u, DI, xpw + (size_t)l*48*DI, nullptr, nullptr, dbc, 48, DI, 0);
        // chunked selective scan (delta fused) + gating
        scan2_kernel<<<BB*DI, 256>>>(xz, u, dbc,
                                     dtw + (size_t)l*DI*DTR, dtb + l*DI,
                                     a_log + (size_t)l*DI*DS, dparam + l*DI, y);
        // ln_in = y @ outw[l]^T + residual(h)
        launch_gemm_small(y, DI, outw + (size_t)l*DM*DI, nullptr, h, ln, DM, DI, 0);
        // h = layernorm(ln_in)
        ln_kernel<<<BL/8, 256>>>(ln, lnw + l*DM, lnb + l*DM, h);
    }

    // out = h @ out_proj_w^T + out_proj_b
    launch_gemm_small(h, DM, out_proj_w, out_proj_b, nullptr, out, DM, DM, 0);
}